// round 14
// baseline (speedup 1.0000x reference)
#include <cuda_runtime.h>
#include <cuda_bf16.h>
#include <cstdint>

#define FD   128
#define NTHR 512
#define MAXN 50048

// ---------------- scratch (no allocations allowed) ----------------
__device__ float g_fbuf[(size_t)MAXN * FD];   // x @ W_in2fac
__device__ float g_conv[(size_t)MAXN * FD];   // segment-sum accumulator

// ---------------- smem layout (uint32 offsets) ----------------
// Per weight matrix: 4 arrays (B0H,B0L,B1H,B1L), each 32 rows x pitch 136 u32.
#define WARR  4352                 /* u32 per array */
#define WOFF1 0                    /* weight 1: 4*WARR = 17408 u32 */
#define WOFF2 17408                /* weight 2 */
#define AH_OFF 34816               /* A hi: 128 rows x pitch 68 */
#define AL_OFF 43520               /* A lo */
#define SW_OFF 34816               /* fp32 w stage (128x132) overlaps A region */
#define B1_OFF 52224               /* bias1 (128 f32) */
#define B2_OFF 52352               /* bias2 */
#define SMEM_U32 52480
#define SMEM_BYTES (SMEM_U32 * 4)  /* 209920 B -> 1 CTA/SM */

__device__ __forceinline__ float ssp_f(float x) {
    float t = __expf(-fabsf(x));
    return fmaxf(x, 0.0f) + __logf(1.0f + t) - 0.6931471805599453f;
}
// two consecutive-k floats -> bf16x2 hi word + bf16x2 residual-lo word
__device__ __forceinline__ void split2(float x0, float x1, uint32_t& hi, uint32_t& lo) {
    __nv_bfloat162 h = __floats2bfloat162_rn(x0, x1);
    float r0 = x0 - __bfloat162float(h.x);
    float r1 = x1 - __bfloat162float(h.y);
    __nv_bfloat162 l = __floats2bfloat162_rn(r0, r1);
    hi = *reinterpret_cast<uint32_t*>(&h);
    lo = *reinterpret_cast<uint32_t*>(&l);
}
__device__ __forceinline__ void mma16(float* d, uint32_t a0, uint32_t a1, uint32_t a2, uint32_t a3,
                                      uint32_t b0, uint32_t b1) {
    asm volatile("mma.sync.aligned.m16n8k16.row.col.f32.bf16.bf16.f32 "
                 "{%0,%1,%2,%3}, {%4,%5,%6,%7}, {%8,%9}, {%0,%1,%2,%3};"
                 : "+f"(d[0]), "+f"(d[1]), "+f"(d[2]), "+f"(d[3])
                 : "r"(a0), "r"(a1), "r"(a2), "r"(a3), "r"(b0), "r"(b1));
}

// ---------------- one-time staging ----------------
// W[k,n] row-major (global) -> resident split-bf16 fragment arrays (full K)
__device__ __forceinline__ void stage_W(uint32_t* sm, int woff,
                                        const float* __restrict__ W, int tid) {
#pragma unroll
    for (int i = 0; i < 16; ++i) {
        int p = tid + i * NTHR;                 // 0..8191
        int n = p & 127, P = p >> 7;            // P = global k-pair 0..63
        float a = W[(size_t)(2 * P) * FD + n];
        float b = W[(size_t)(2 * P + 1) * FD + n];
        uint32_t hi, lo; split2(a, b, hi, lo);
        int kc = P >> 4, pp = P & 15, s = pp >> 3, q = pp & 7;
        int half = q >> 2;
        int idx = (kc * 8 + s * 4 + (q & 3)) * 136 + n;
        sm[woff + half * 2 * WARR + idx] = hi;
        sm[woff + half * 2 * WARR + WARR + idx] = lo;
    }
}
// A[row0.., 0:128] row-major -> resident split-bf16 A (full K), zero-pad rows >= nv
__device__ __forceinline__ void stage_A(uint32_t* sm, const float* __restrict__ A,
                                        int row0, int nv, int tid) {
#pragma unroll
    for (int i = 0; i < 16; ++i) {
        int p = tid + i * NTHR;                 // 0..8191
        int row = p >> 6, kp = p & 63;
        float2 v = make_float2(0.f, 0.f);
        if (row < nv) v = *(const float2*)(A + (size_t)(row0 + row) * FD + kp * 2);
        uint32_t hi, lo; split2(v.x, v.y, hi, lo);
        int kc = kp >> 4, pp = kp & 15, s = pp >> 3, q = pp & 7;
        int col = kc * 16 + s * 8 + (q & 3) * 2 + (q >> 2);
        sm[AH_OFF + row * 68 + col] = hi;
        sm[AL_OFF + row * 68 + col] = lo;
    }
}

// ---------------- resident-everything GEMM: no syncs, no stores ----------------
__device__ __forceinline__ void gemm_res(const uint32_t* sm, int woff,
                                         float (&acc)[2][4][4],
                                         int mrow, int ncol0, int qr, int qc) {
#pragma unroll
    for (int kc = 0; kc < 4; ++kc) {
#pragma unroll
        for (int s = 0; s < 2; ++s) {
            uint2 Ah[2][2], Al[2][2];
            int c = kc * 16 + s * 8 + qc * 2;
#pragma unroll
            for (int mi = 0; mi < 2; ++mi) {
                int r0 = mrow + mi * 16 + qr;
                Ah[mi][0] = *(const uint2*)(sm + AH_OFF + r0 * 68 + c);
                Ah[mi][1] = *(const uint2*)(sm + AH_OFF + (r0 + 8) * 68 + c);
                Al[mi][0] = *(const uint2*)(sm + AL_OFF + r0 * 68 + c);
                Al[mi][1] = *(const uint2*)(sm + AL_OFF + (r0 + 8) * 68 + c);
            }
            int brow = (kc * 8 + s * 4 + qc) * 136 + ncol0 + qr;
#pragma unroll
            for (int nb = 0; nb < 4; ++nb) {
                uint32_t b0h = sm[woff + brow + nb * 8];
                uint32_t b0l = sm[woff + WARR + brow + nb * 8];
                uint32_t b1h = sm[woff + 2 * WARR + brow + nb * 8];
                uint32_t b1l = sm[woff + 3 * WARR + brow + nb * 8];
#pragma unroll
                for (int mi = 0; mi < 2; ++mi) {
                    mma16(acc[mi][nb], Ah[mi][0].x, Ah[mi][1].x, Ah[mi][0].y, Ah[mi][1].y, b0l, b1l);
                    mma16(acc[mi][nb], Al[mi][0].x, Al[mi][1].x, Al[mi][0].y, Al[mi][1].y, b0h, b1h);
                    mma16(acc[mi][nb], Ah[mi][0].x, Ah[mi][1].x, Ah[mi][0].y, Ah[mi][1].y, b0h, b1h);
                }
            }
        }
    }
}

// stage h fragments (post-ssp) back into resident A (proven R11 mapping)
__device__ __forceinline__ void stage_h(uint32_t* sm, const float (&h)[2][4][4],
                                        int wid_n, int mrow, int qr, int qc) {
#pragma unroll
    for (int mi = 0; mi < 2; ++mi)
#pragma unroll
        for (int nb = 0; nb < 4; ++nb) {
            int col = wid_n * 16 + (nb >> 1) * 8 + qc * 2 + (nb & 1);
            int rlo = mrow + mi * 16 + qr;
            uint32_t hi, lo;
            split2(h[mi][nb][0], h[mi][nb][1], hi, lo);
            sm[AH_OFF + rlo * 68 + col] = hi;
            sm[AL_OFF + rlo * 68 + col] = lo;
            split2(h[mi][nb][2], h[mi][nb][3], hi, lo);
            sm[AH_OFF + (rlo + 8) * 68 + col] = hi;
            sm[AL_OFF + (rlo + 8) * 68 + col] = lo;
        }
}

__device__ __forceinline__ void bias_ssp(float (&a)[2][4][4], const float* __restrict__ b,
                                         int ncol0, int qc) {
#pragma unroll
    for (int nb = 0; nb < 4; ++nb) {
        float2 bb = *(const float2*)(b + ncol0 + nb * 8 + 2 * qc);
#pragma unroll
        for (int mi = 0; mi < 2; ++mi) {
            a[mi][nb][0] = ssp_f(a[mi][nb][0] + bb.x);
            a[mi][nb][1] = ssp_f(a[mi][nb][1] + bb.y);
            a[mi][nb][2] = ssp_f(a[mi][nb][2] + bb.x);
            a[mi][nb][3] = ssp_f(a[mi][nb][3] + bb.y);
        }
    }
}

// ---------------- kernels ----------------
__global__ void k_zero(int n4) {
    int i = blockIdx.x * blockDim.x + threadIdx.x;
    if (i < n4) ((float4*)g_conv)[i] = make_float4(0.f, 0.f, 0.f, 0.f);
}

__global__ void __launch_bounds__(NTHR, 1) k_in2fac(const float* __restrict__ x,
                                                    const float* __restrict__ Wi,
                                                    int N, int nTiles) {
    extern __shared__ uint32_t sm[];
    int tid = threadIdx.x, lane = tid & 31, wid = tid >> 5;
    int qr = lane >> 2, qc = lane & 3;
    int mrow = (wid >> 2) * 32, ncol0 = (wid & 3) * 32;

    stage_W(sm, WOFF1, Wi, tid);
    __syncthreads();

    for (int t = blockIdx.x; t < nTiles; t += gridDim.x) {
        int row0 = t * 128;
        stage_A(sm, x, row0, min(128, N - row0), tid);
        __syncthreads();

        float acc[2][4][4] = {};
        gemm_res(sm, WOFF1, acc, mrow, ncol0, qr, qc);

#pragma unroll
        for (int mi = 0; mi < 2; ++mi)
#pragma unroll
            for (int rh = 0; rh < 2; ++rh) {
                int row = row0 + mrow + mi * 16 + qr + rh * 8;
                if (row < N) {
#pragma unroll
                    for (int nb = 0; nb < 4; ++nb)
                        *(float2*)(g_fbuf + (size_t)row * FD + ncol0 + nb * 8 + 2 * qc) =
                            make_float2(acc[mi][nb][rh * 2], acc[mi][nb][rh * 2 + 1]);
                }
            }
        __syncthreads();   // A region reused next tile
    }
}

__global__ void __launch_bounds__(NTHR, 1) k_edge(const float* __restrict__ dijk,
                                                  const float* __restrict__ W1,
                                                  const float* __restrict__ b1,
                                                  const float* __restrict__ W2,
                                                  const float* __restrict__ b2,
                                                  const int* __restrict__ idx_j,
                                                  const int* __restrict__ seg_i,
                                                  int E, int nTiles) {
    extern __shared__ uint32_t sm[];
    int tid = threadIdx.x, lane = tid & 31, wid = tid >> 5;
    int qr = lane >> 2, qc = lane & 3;
    int mrow = (wid >> 2) * 32, ncol0 = (wid & 3) * 32;

    stage_W(sm, WOFF1, W1, tid);
    stage_W(sm, WOFF2, W2, tid);
    if (tid < FD) {
        ((float*)(sm + B1_OFF))[tid] = b1[tid];
        ((float*)(sm + B2_OFF))[tid] = b2[tid];
    }
    __syncthreads();

    const float* bb1 = (const float*)(sm + B1_OFF);
    const float* bb2 = (const float*)(sm + B2_OFF);
    float* sW = (float*)(sm + SW_OFF);
    int tx = tid & 31, ty = tid >> 5;    // RLE epilogue mapping
    int col0 = tx * 4;

    for (int t = blockIdx.x; t < nTiles; t += gridDim.x) {
        int e0 = t * 128;
        stage_A(sm, dijk, e0, min(128, E - e0), tid);
        __syncthreads();

        // h = ssp(dijk @ W1 + b1)
        float acc[2][4][4] = {};
        gemm_res(sm, WOFF1, acc, mrow, ncol0, qr, qc);
        bias_ssp(acc, bb1, ncol0, qc);
        __syncthreads();                 // all warps done reading A
        stage_h(sm, acc, wid & 3, mrow, qr, qc);
        __syncthreads();

        // w = ssp(h @ W2 + b2)   (seg_j == arange -> first segment_sum identity)
#pragma unroll
        for (int mi = 0; mi < 2; ++mi)
#pragma unroll
            for (int nb = 0; nb < 4; ++nb)
#pragma unroll
                for (int r = 0; r < 4; ++r) acc[mi][nb][r] = 0.f;
        gemm_res(sm, WOFF2, acc, mrow, ncol0, qr, qc);
        bias_ssp(acc, bb2, ncol0, qc);
        __syncthreads();                 // all warps done reading h before sW overwrite

        // stage w to fp32 smem (overlaps A region)
#pragma unroll
        for (int mi = 0; mi < 2; ++mi)
#pragma unroll
            for (int rh = 0; rh < 2; ++rh) {
                int row = mrow + mi * 16 + qr + rh * 8;
#pragma unroll
                for (int nb = 0; nb < 4; ++nb)
                    *(float2*)(sW + row * 132 + ncol0 + nb * 8 + 2 * qc) =
                        make_float2(acc[mi][nb][rh * 2], acc[mi][nb][rh * 2 + 1]);
            }
        __syncthreads();

        // wf = w * f[idx_j]; RLE-compressed segmented atomicAdd into g_conv[seg_i]
        {
            float accv[4];
            int cur = -1;
#pragma unroll
            for (int rr = 0; rr < 8; ++rr) {
                int lr = ty * 8 + rr;
                int e = e0 + lr;
                if (e < E) {
                    int j = idx_j[e];
                    float4 f0 = *(const float4*)(g_fbuf + (size_t)j * FD + col0);
                    float4 w0 = *(const float4*)(sW + lr * 132 + col0);
                    float wf[4] = { w0.x * f0.x, w0.y * f0.y, w0.z * f0.z, w0.w * f0.w };
                    int s = seg_i[e];
                    if (s != cur) {
                        if (cur >= 0) {
                            float* dst = g_conv + (size_t)cur * FD + col0;
#pragma unroll
                            for (int c = 0; c < 4; ++c) atomicAdd(dst + c, accv[c]);
                        }
                        cur = s;
#pragma unroll
                        for (int c = 0; c < 4; ++c) accv[c] = wf[c];
                    } else {
#pragma unroll
                        for (int c = 0; c < 4; ++c) accv[c] += wf[c];
                    }
                }
            }
            if (cur >= 0) {
                float* dst = g_conv + (size_t)cur * FD + col0;
#pragma unroll
                for (int c = 0; c < 4; ++c) atomicAdd(dst + c, accv[c]);
            }
        }
        __syncthreads();                 // sW/A region reused next tile
    }
}

__global__ void __launch_bounds__(NTHR, 1) k_atom(const float* __restrict__ x,
                                                  const float* __restrict__ Wf,
                                                  const float* __restrict__ bf,
                                                  const float* __restrict__ Wd,
                                                  const float* __restrict__ bd,
                                                  float* __restrict__ out,
                                                  int N, int nTiles, int hasv) {
    extern __shared__ uint32_t sm[];
    int tid = threadIdx.x, lane = tid & 31, wid = tid >> 5;
    int qr = lane >> 2, qc = lane & 3;
    int mrow = (wid >> 2) * 32, ncol0 = (wid & 3) * 32;

    stage_W(sm, WOFF1, Wf, tid);
    stage_W(sm, WOFF2, Wd, tid);
    if (tid < FD) {
        ((float*)(sm + B1_OFF))[tid] = bf[tid];
        ((float*)(sm + B2_OFF))[tid] = bd[tid];
    }
    __syncthreads();

    const float* bb1 = (const float*)(sm + B1_OFF);
    const float* bb2 = (const float*)(sm + B2_OFF);

    for (int t = blockIdx.x; t < nTiles; t += gridDim.x) {
        int row0 = t * 128;
        stage_A(sm, (const float*)g_conv, row0, min(128, N - row0), tid);
        __syncthreads();

        // c = ssp(conv @ W_fac2out + b_fac2out)
        float acc[2][4][4] = {};
        gemm_res(sm, WOFF1, acc, mrow, ncol0, qr, qc);
        bias_ssp(acc, bb1, ncol0, qc);
        __syncthreads();
        stage_h(sm, acc, wid & 3, mrow, qr, qc);
        __syncthreads();

        // v = c @ W_dense + b_dense;  y = x + v
#pragma unroll
        for (int mi = 0; mi < 2; ++mi)
#pragma unroll
            for (int nb = 0; nb < 4; ++nb)
#pragma unroll
                for (int r = 0; r < 4; ++r) acc[mi][nb][r] = 0.f;
        gemm_res(sm, WOFF2, acc, mrow, ncol0, qr, qc);

#pragma unroll
        for (int mi = 0; mi < 2; ++mi)
#pragma unroll
            for (int rh = 0; rh < 2; ++rh) {
                int row = row0 + mrow + mi * 16 + qr + rh * 8;
                if (row < N) {
#pragma unroll
                    for (int nb = 0; nb < 4; ++nb) {
                        int col = ncol0 + nb * 8 + 2 * qc;
                        float2 bb = *(const float2*)(bb2 + col);
                        float2 xv = *(const float2*)(x + (size_t)row * FD + col);
                        float2 vv = make_float2(acc[mi][nb][rh * 2] + bb.x,
                                                acc[mi][nb][rh * 2 + 1] + bb.y);
                        *(float2*)(out + (size_t)row * FD + col) =
                            make_float2(xv.x + vv.x, xv.y + vv.y);
                        if (hasv)
                            *(float2*)(out + (size_t)N * FD + (size_t)row * FD + col) = vv;
                    }
                }
            }
        __syncthreads();                 // A region reused next tile
    }
}

extern "C" void kernel_launch(void* const* d_in, const int* in_sizes, int n_in,
                              void* d_out, int out_size) {
    const float* x    = (const float*)d_in[0];
    const float* dijk = (const float*)d_in[1];
    const int* idx_j  = (const int*)d_in[2];
    const int* seg_i  = (const int*)d_in[3];
    int wb = 4;
    while (wb < n_in && in_sizes[wb] != FD * FD) ++wb;
    const float* W1 = (const float*)d_in[wb + 0];
    const float* b1 = (const float*)d_in[wb + 1];
    const float* W2 = (const float*)d_in[wb + 2];
    const float* b2 = (const float*)d_in[wb + 3];
    const float* Wi = (const float*)d_in[wb + 4];
    const float* Wf = (const float*)d_in[wb + 5];
    const float* bf = (const float*)d_in[wb + 6];
    const float* Wd = (const float*)d_in[wb + 7];
    const float* bd = (const float*)d_in[wb + 8];

    int N = in_sizes[0] / FD;
    int E = in_sizes[1] / FD;
    float* out = (float*)d_out;
    int hasv = (out_size >= 2 * N * FD) ? 1 : 0;

    cudaFuncSetAttribute(k_in2fac, cudaFuncAttributeMaxDynamicSharedMemorySize, SMEM_BYTES);
    cudaFuncSetAttribute(k_edge,   cudaFuncAttributeMaxDynamicSharedMemorySize, SMEM_BYTES);
    cudaFuncSetAttribute(k_atom,   cudaFuncAttributeMaxDynamicSharedMemorySize, SMEM_BYTES);

    int nTilesN = (N + 127) / 128;
    int nTilesE = (E + 127) / 128;
    int n4 = (N * FD) / 4;
    int gN = nTilesN < 148 ? nTilesN : 148;
    int gE = nTilesE < 148 ? nTilesE : 148;

    k_zero<<<(n4 + 255) / 256, 256>>>(n4);
    k_in2fac<<<gN, NTHR, SMEM_BYTES>>>(x, Wi, N, nTilesN);
    k_edge<<<gE, NTHR, SMEM_BYTES>>>(dijk, W1, b1, W2, b2, idx_j, seg_i, E, nTilesE);
    k_atom<<<gN, NTHR, SMEM_BYTES>>>(x, Wf, bf, Wd, bd, out, N, nTilesN, hasv);
}

// round 15
// speedup vs baseline: 1.0055x; 1.0055x over previous
#include <cuda_runtime.h>
#include <cuda_bf16.h>
#include <cstdint>

#define FD   128
#define NTHR 512
#define MAXN 50048

// ---------------- scratch (no allocations allowed) ----------------
__device__ float g_fbuf[(size_t)MAXN * FD];   // x @ W_in2fac
__device__ float g_conv[(size_t)MAXN * FD];   // segment-sum accumulator

// ---------------- smem layout (uint32 offsets) ----------------
// Per weight matrix: 4 arrays (B0H,B0L,B1H,B1L), each 32 rows x pitch 136 u32.
#define WARR  4352                 /* u32 per array */
#define WOFF1 0                    /* weight 1: 4*WARR = 17408 u32 */
#define WOFF2 17408                /* weight 2 */
#define AH_OFF 34816               /* A hi: 128 rows x pitch 68 */
#define AL_OFF 43520               /* A lo */
#define SW_OFF 34816               /* fp32 w stage (128x132) overlaps A region */
#define B1_OFF 52224               /* bias1 (128 f32) */
#define B2_OFF 52352               /* bias2 */
#define SMEM_U32 52480
#define SMEM_BYTES (SMEM_U32 * 4)  /* 209920 B -> 1 CTA/SM */

__device__ __forceinline__ float ssp_f(float x) {
    float t = __expf(-fabsf(x));
    return fmaxf(x, 0.0f) + __logf(1.0f + t) - 0.6931471805599453f;
}
// two consecutive-k floats -> bf16x2 hi word + bf16x2 residual-lo word
__device__ __forceinline__ void split2(float x0, float x1, uint32_t& hi, uint32_t& lo) {
    __nv_bfloat162 h = __floats2bfloat162_rn(x0, x1);
    float r0 = x0 - __bfloat162float(h.x);
    float r1 = x1 - __bfloat162float(h.y);
    __nv_bfloat162 l = __floats2bfloat162_rn(r0, r1);
    hi = *reinterpret_cast<uint32_t*>(&h);
    lo = *reinterpret_cast<uint32_t*>(&l);
}
__device__ __forceinline__ void mma16(float* d, uint32_t a0, uint32_t a1, uint32_t a2, uint32_t a3,
                                      uint32_t b0, uint32_t b1) {
    asm volatile("mma.sync.aligned.m16n8k16.row.col.f32.bf16.bf16.f32 "
                 "{%0,%1,%2,%3}, {%4,%5,%6,%7}, {%8,%9}, {%0,%1,%2,%3};"
                 : "+f"(d[0]), "+f"(d[1]), "+f"(d[2]), "+f"(d[3])
                 : "r"(a0), "r"(a1), "r"(a2), "r"(a3), "r"(b0), "r"(b1));
}

// ---------------- one-time staging ----------------
// W[k,n] row-major (global) -> resident split-bf16 fragment arrays (full K)
__device__ __forceinline__ void stage_W(uint32_t* sm, int woff,
                                        const float* __restrict__ W, int tid) {
#pragma unroll
    for (int i = 0; i < 16; ++i) {
        int p = tid + i * NTHR;                 // 0..8191
        int n = p & 127, P = p >> 7;            // P = global k-pair 0..63
        float a = W[(size_t)(2 * P) * FD + n];
        float b = W[(size_t)(2 * P + 1) * FD + n];
        uint32_t hi, lo; split2(a, b, hi, lo);
        int kc = P >> 4, pp = P & 15, s = pp >> 3, q = pp & 7;
        int half = q >> 2;
        int idx = (kc * 8 + s * 4 + (q & 3)) * 136 + n;
        sm[woff + half * 2 * WARR + idx] = hi;
        sm[woff + half * 2 * WARR + WARR + idx] = lo;
    }
}
// A[row0.., 0:128] row-major -> resident split-bf16 A (full K), zero-pad rows >= nv
__device__ __forceinline__ void stage_A(uint32_t* sm, const float* __restrict__ A,
                                        int row0, int nv, int tid) {
#pragma unroll
    for (int i = 0; i < 16; ++i) {
        int p = tid + i * NTHR;                 // 0..8191
        int row = p >> 6, kp = p & 63;
        float2 v = make_float2(0.f, 0.f);
        if (row < nv) v = *(const float2*)(A + (size_t)(row0 + row) * FD + kp * 2);
        uint32_t hi, lo; split2(v.x, v.y, hi, lo);
        int kc = kp >> 4, pp = kp & 15, s = pp >> 3, q = pp & 7;
        int col = kc * 16 + s * 8 + (q & 3) * 2 + (q >> 2);
        sm[AH_OFF + row * 68 + col] = hi;
        sm[AL_OFF + row * 68 + col] = lo;
    }
}

// ---------------- resident-everything GEMM: no syncs, no stores ----------------
__device__ __forceinline__ void gemm_res(const uint32_t* sm, int woff,
                                         float (&acc)[2][4][4],
                                         int mrow, int ncol0, int qr, int qc) {
#pragma unroll
    for (int kc = 0; kc < 4; ++kc) {
#pragma unroll
        for (int s = 0; s < 2; ++s) {
            uint2 Ah[2][2], Al[2][2];
            int c = kc * 16 + s * 8 + qc * 2;
#pragma unroll
            for (int mi = 0; mi < 2; ++mi) {
                int r0 = mrow + mi * 16 + qr;
                Ah[mi][0] = *(const uint2*)(sm + AH_OFF + r0 * 68 + c);
                Ah[mi][1] = *(const uint2*)(sm + AH_OFF + (r0 + 8) * 68 + c);
                Al[mi][0] = *(const uint2*)(sm + AL_OFF + r0 * 68 + c);
                Al[mi][1] = *(const uint2*)(sm + AL_OFF + (r0 + 8) * 68 + c);
            }
            int brow = (kc * 8 + s * 4 + qc) * 136 + ncol0 + qr;
#pragma unroll
            for (int nb = 0; nb < 4; ++nb) {
                uint32_t b0h = sm[woff + brow + nb * 8];
                uint32_t b0l = sm[woff + WARR + brow + nb * 8];
                uint32_t b1h = sm[woff + 2 * WARR + brow + nb * 8];
                uint32_t b1l = sm[woff + 3 * WARR + brow + nb * 8];
#pragma unroll
                for (int mi = 0; mi < 2; ++mi) {
                    mma16(acc[mi][nb], Ah[mi][0].x, Ah[mi][1].x, Ah[mi][0].y, Ah[mi][1].y, b0l, b1l);
                    mma16(acc[mi][nb], Al[mi][0].x, Al[mi][1].x, Al[mi][0].y, Al[mi][1].y, b0h, b1h);
                    mma16(acc[mi][nb], Ah[mi][0].x, Ah[mi][1].x, Ah[mi][0].y, Ah[mi][1].y, b0h, b1h);
                }
            }
        }
    }
}

// stage h fragments (post-ssp) back into resident A (proven R11 mapping)
__device__ __forceinline__ void stage_h(uint32_t* sm, const float (&h)[2][4][4],
                                        int wid_n, int mrow, int qr, int qc) {
#pragma unroll
    for (int mi = 0; mi < 2; ++mi)
#pragma unroll
        for (int nb = 0; nb < 4; ++nb) {
            int col = wid_n * 16 + (nb >> 1) * 8 + qc * 2 + (nb & 1);
            int rlo = mrow + mi * 16 + qr;
            uint32_t hi, lo;
            split2(h[mi][nb][0], h[mi][nb][1], hi, lo);
            sm[AH_OFF + rlo * 68 + col] = hi;
            sm[AL_OFF + rlo * 68 + col] = lo;
            split2(h[mi][nb][2], h[mi][nb][3], hi, lo);
            sm[AH_OFF + (rlo + 8) * 68 + col] = hi;
            sm[AL_OFF + (rlo + 8) * 68 + col] = lo;
        }
}

__device__ __forceinline__ void bias_ssp(float (&a)[2][4][4], const float* __restrict__ b,
                                         int ncol0, int qc) {
#pragma unroll
    for (int nb = 0; nb < 4; ++nb) {
        float2 bb = *(const float2*)(b + ncol0 + nb * 8 + 2 * qc);
#pragma unroll
        for (int mi = 0; mi < 2; ++mi) {
            a[mi][nb][0] = ssp_f(a[mi][nb][0] + bb.x);
            a[mi][nb][1] = ssp_f(a[mi][nb][1] + bb.y);
            a[mi][nb][2] = ssp_f(a[mi][nb][2] + bb.x);
            a[mi][nb][3] = ssp_f(a[mi][nb][3] + bb.y);
        }
    }
}

// ---------------- kernels ----------------
__global__ void k_zero(int n4) {
    int i = blockIdx.x * blockDim.x + threadIdx.x;
    if (i < n4) ((float4*)g_conv)[i] = make_float4(0.f, 0.f, 0.f, 0.f);
}

__global__ void __launch_bounds__(NTHR, 1) k_in2fac(const float* __restrict__ x,
                                                    const float* __restrict__ Wi,
                                                    int N, int nTiles) {
    extern __shared__ uint32_t sm[];
    int tid = threadIdx.x, lane = tid & 31, wid = tid >> 5;
    int qr = lane >> 2, qc = lane & 3;
    int mrow = (wid >> 2) * 32, ncol0 = (wid & 3) * 32;

    stage_W(sm, WOFF1, Wi, tid);
    __syncthreads();

    for (int t = blockIdx.x; t < nTiles; t += gridDim.x) {
        int row0 = t * 128;
        stage_A(sm, x, row0, min(128, N - row0), tid);
        __syncthreads();

        float acc[2][4][4] = {};
        gemm_res(sm, WOFF1, acc, mrow, ncol0, qr, qc);

#pragma unroll
        for (int mi = 0; mi < 2; ++mi)
#pragma unroll
            for (int rh = 0; rh < 2; ++rh) {
                int row = row0 + mrow + mi * 16 + qr + rh * 8;
                if (row < N) {
#pragma unroll
                    for (int nb = 0; nb < 4; ++nb)
                        *(float2*)(g_fbuf + (size_t)row * FD + ncol0 + nb * 8 + 2 * qc) =
                            make_float2(acc[mi][nb][rh * 2], acc[mi][nb][rh * 2 + 1]);
                }
            }
        __syncthreads();   // A region reused next tile
    }
}

__global__ void __launch_bounds__(NTHR, 1) k_edge(const float* __restrict__ dijk,
                                                  const float* __restrict__ W1,
                                                  const float* __restrict__ b1,
                                                  const float* __restrict__ W2,
                                                  const float* __restrict__ b2,
                                                  const int* __restrict__ idx_j,
                                                  const int* __restrict__ seg_i,
                                                  int E, int nTiles) {
    extern __shared__ uint32_t sm[];
    int tid = threadIdx.x, lane = tid & 31, wid = tid >> 5;
    int qr = lane >> 2, qc = lane & 3;
    int mrow = (wid >> 2) * 32, ncol0 = (wid & 3) * 32;

    stage_W(sm, WOFF1, W1, tid);
    stage_W(sm, WOFF2, W2, tid);
    if (tid < FD) {
        ((float*)(sm + B1_OFF))[tid] = b1[tid];
        ((float*)(sm + B2_OFF))[tid] = b2[tid];
    }
    __syncthreads();

    const float* bb1 = (const float*)(sm + B1_OFF);
    const float* bb2 = (const float*)(sm + B2_OFF);
    float* sW = (float*)(sm + SW_OFF);
    int tx = tid & 31, ty = tid >> 5;    // RLE epilogue mapping
    int col0 = tx * 4;

    for (int t = blockIdx.x; t < nTiles; t += gridDim.x) {
        int e0 = t * 128;
        stage_A(sm, dijk, e0, min(128, E - e0), tid);
        __syncthreads();

        // h = ssp(dijk @ W1 + b1)
        float acc[2][4][4] = {};
        gemm_res(sm, WOFF1, acc, mrow, ncol0, qr, qc);
        bias_ssp(acc, bb1, ncol0, qc);
        __syncthreads();                 // all warps done reading A
        stage_h(sm, acc, wid & 3, mrow, qr, qc);
        __syncthreads();

        // w = ssp(h @ W2 + b2)   (seg_j == arange -> first segment_sum identity)
#pragma unroll
        for (int mi = 0; mi < 2; ++mi)
#pragma unroll
            for (int nb = 0; nb < 4; ++nb)
#pragma unroll
                for (int r = 0; r < 4; ++r) acc[mi][nb][r] = 0.f;
        gemm_res(sm, WOFF2, acc, mrow, ncol0, qr, qc);
        bias_ssp(acc, bb2, ncol0, qc);
        __syncthreads();                 // all warps done reading h before sW overwrite

        // stage w to fp32 smem (overlaps A region)
#pragma unroll
        for (int mi = 0; mi < 2; ++mi)
#pragma unroll
            for (int rh = 0; rh < 2; ++rh) {
                int row = mrow + mi * 16 + qr + rh * 8;
#pragma unroll
                for (int nb = 0; nb < 4; ++nb)
                    *(float2*)(sW + row * 132 + ncol0 + nb * 8 + 2 * qc) =
                        make_float2(acc[mi][nb][rh * 2], acc[mi][nb][rh * 2 + 1]);
            }
        __syncthreads();

        // wf = w * f[idx_j]; RLE-compressed segmented atomicAdd into g_conv[seg_i]
        {
            float accv[4];
            int cur = -1;
#pragma unroll
            for (int rr = 0; rr < 8; ++rr) {
                int lr = ty * 8 + rr;
                int e = e0 + lr;
                if (e < E) {
                    int j = idx_j[e];
                    float4 f0 = *(const float4*)(g_fbuf + (size_t)j * FD + col0);
                    float4 w0 = *(const float4*)(sW + lr * 132 + col0);
                    float wf[4] = { w0.x * f0.x, w0.y * f0.y, w0.z * f0.z, w0.w * f0.w };
                    int s = seg_i[e];
                    if (s != cur) {
                        if (cur >= 0) {
                            float* dst = g_conv + (size_t)cur * FD + col0;
#pragma unroll
                            for (int c = 0; c < 4; ++c) atomicAdd(dst + c, accv[c]);
                        }
                        cur = s;
#pragma unroll
                        for (int c = 0; c < 4; ++c) accv[c] = wf[c];
                    } else {
#pragma unroll
                        for (int c = 0; c < 4; ++c) accv[c] += wf[c];
                    }
                }
            }
            if (cur >= 0) {
                float* dst = g_conv + (size_t)cur * FD + col0;
#pragma unroll
                for (int c = 0; c < 4; ++c) atomicAdd(dst + c, accv[c]);
            }
        }
        __syncthreads();                 // sW/A region reused next tile
    }
}

__global__ void __launch_bounds__(NTHR, 1) k_atom(const float* __restrict__ x,
                                                  const float* __restrict__ Wf,
                                                  const float* __restrict__ bf,
                                                  const float* __restrict__ Wd,
                                                  const float* __restrict__ bd,
                                                  float* __restrict__ out,
                                                  int N, int nTiles, int hasv) {
    extern __shared__ uint32_t sm[];
    int tid = threadIdx.x, lane = tid & 31, wid = tid >> 5;
    int qr = lane >> 2, qc = lane & 3;
    int mrow = (wid >> 2) * 32, ncol0 = (wid & 3) * 32;

    stage_W(sm, WOFF1, Wf, tid);
    stage_W(sm, WOFF2, Wd, tid);
    if (tid < FD) {
        ((float*)(sm + B1_OFF))[tid] = bf[tid];
        ((float*)(sm + B2_OFF))[tid] = bd[tid];
    }
    __syncthreads();

    const float* bb1 = (const float*)(sm + B1_OFF);
    const float* bb2 = (const float*)(sm + B2_OFF);

    for (int t = blockIdx.x; t < nTiles; t += gridDim.x) {
        int row0 = t * 128;
        stage_A(sm, (const float*)g_conv, row0, min(128, N - row0), tid);
        __syncthreads();

        // c = ssp(conv @ W_fac2out + b_fac2out)
        float acc[2][4][4] = {};
        gemm_res(sm, WOFF1, acc, mrow, ncol0, qr, qc);
        bias_ssp(acc, bb1, ncol0, qc);
        __syncthreads();
        stage_h(sm, acc, wid & 3, mrow, qr, qc);
        __syncthreads();

        // v = c @ W_dense + b_dense;  y = x + v
#pragma unroll
        for (int mi = 0; mi < 2; ++mi)
#pragma unroll
            for (int nb = 0; nb < 4; ++nb)
#pragma unroll
                for (int r = 0; r < 4; ++r) acc[mi][nb][r] = 0.f;
        gemm_res(sm, WOFF2, acc, mrow, ncol0, qr, qc);

#pragma unroll
        for (int mi = 0; mi < 2; ++mi)
#pragma unroll
            for (int rh = 0; rh < 2; ++rh) {
                int row = row0 + mrow + mi * 16 + qr + rh * 8;
                if (row < N) {
#pragma unroll
                    for (int nb = 0; nb < 4; ++nb) {
                        int col = ncol0 + nb * 8 + 2 * qc;
                        float2 bb = *(const float2*)(bb2 + col);
                        float2 xv = *(const float2*)(x + (size_t)row * FD + col);
                        float2 vv = make_float2(acc[mi][nb][rh * 2] + bb.x,
                                                acc[mi][nb][rh * 2 + 1] + bb.y);
                        *(float2*)(out + (size_t)row * FD + col) =
                            make_float2(xv.x + vv.x, xv.y + vv.y);
                        if (hasv)
                            *(float2*)(out + (size_t)N * FD + (size_t)row * FD + col) = vv;
                    }
                }
            }
        __syncthreads();                 // A region reused next tile
    }
}

extern "C" void kernel_launch(void* const* d_in, const int* in_sizes, int n_in,
                              void* d_out, int out_size) {
    const float* x    = (const float*)d_in[0];
    const float* dijk = (const float*)d_in[1];
    const int* idx_j  = (const int*)d_in[2];
    const int* seg_i  = (const int*)d_in[3];
    int wb = 4;
    while (wb < n_in && in_sizes[wb] != FD * FD) ++wb;
    const float* W1 = (const float*)d_in[wb + 0];
    const float* b1 = (const float*)d_in[wb + 1];
    const float* W2 = (const float*)d_in[wb + 2];
    const float* b2 = (const float*)d_in[wb + 3];
    const float* Wi = (const float*)d_in[wb + 4];
    const float* Wf = (const float*)d_in[wb + 5];
    const float* bf = (const float*)d_in[wb + 6];
    const float* Wd = (const float*)d_in[wb + 7];
    const float* bd = (const float*)d_in[wb + 8];

    int N = in_sizes[0] / FD;
    int E = in_sizes[1] / FD;
    float* out = (float*)d_out;
    int hasv = (out_size >= 2 * N * FD) ? 1 : 0;

    cudaFuncSetAttribute(k_in2fac, cudaFuncAttributeMaxDynamicSharedMemorySize, SMEM_BYTES);
    cudaFuncSetAttribute(k_edge,   cudaFuncAttributeMaxDynamicSharedMemorySize, SMEM_BYTES);
    cudaFuncSetAttribute(k_atom,   cudaFuncAttributeMaxDynamicSharedMemorySize, SMEM_BYTES);

    int nTilesN = (N + 127) / 128;
    int nTilesE = (E + 127) / 128;
    int n4 = (N * FD) / 4;
    int gN = nTilesN < 148 ? nTilesN : 148;
    int gE = nTilesE < 148 ? nTilesE : 148;

    k_zero<<<(n4 + 255) / 256, 256>>>(n4);
    k_in2fac<<<gN, NTHR, SMEM_BYTES>>>(x, Wi, N, nTilesN);
    k_edge<<<gE, NTHR, SMEM_BYTES>>>(dijk, W1, b1, W2, b2, idx_j, seg_i, E, nTilesE);
    k_atom<<<gN, NTHR, SMEM_BYTES>>>(x, Wf, bf, Wd, bd, out, N, nTilesN, hasv);
}

// round 16
// speedup vs baseline: 1.0072x; 1.0018x over previous
#include <cuda_runtime.h>
#include <cuda_bf16.h>
#include <cstdint>

#define FD   128
#define NTHR 512
#define MAXN 50048

// ---------------- scratch (no allocations allowed) ----------------
__device__ float g_fbuf[(size_t)MAXN * FD];   // x @ W_in2fac
__device__ float g_conv[(size_t)MAXN * FD];   // segment-sum accumulator

// ---------------- smem layout (uint32 offsets) ----------------
// Per weight matrix: 4 arrays (B0H,B0L,B1H,B1L), each 32 rows x pitch 136 u32.
#define WARR  4352                 /* u32 per array */
#define WOFF1 0                    /* weight 1: 4*WARR = 17408 u32 */
#define WOFF2 17408                /* weight 2 */
#define AH_OFF 34816               /* A hi: 128 rows x pitch 68 */
#define AL_OFF 43520               /* A lo */
#define SW_OFF 34816               /* fp32 w stage (128x132) overlaps A region */
#define B1_OFF 52224               /* bias1 (128 f32) */
#define B2_OFF 52352               /* bias2 */
#define SMEM_U32 52480
#define SMEM_BYTES (SMEM_U32 * 4)  /* 209920 B -> 1 CTA/SM */

__device__ __forceinline__ float ssp_f(float x) {
    float t = __expf(-fabsf(x));
    return fmaxf(x, 0.0f) + __logf(1.0f + t) - 0.6931471805599453f;
}
// two consecutive-k floats -> bf16x2 hi word + bf16x2 residual-lo word
__device__ __forceinline__ void split2(float x0, float x1, uint32_t& hi, uint32_t& lo) {
    __nv_bfloat162 h = __floats2bfloat162_rn(x0, x1);
    float r0 = x0 - __bfloat162float(h.x);
    float r1 = x1 - __bfloat162float(h.y);
    __nv_bfloat162 l = __floats2bfloat162_rn(r0, r1);
    hi = *reinterpret_cast<uint32_t*>(&h);
    lo = *reinterpret_cast<uint32_t*>(&l);
}
__device__ __forceinline__ void mma16(float* d, uint32_t a0, uint32_t a1, uint32_t a2, uint32_t a3,
                                      uint32_t b0, uint32_t b1) {
    asm volatile("mma.sync.aligned.m16n8k16.row.col.f32.bf16.bf16.f32 "
                 "{%0,%1,%2,%3}, {%4,%5,%6,%7}, {%8,%9}, {%0,%1,%2,%3};"
                 : "+f"(d[0]), "+f"(d[1]), "+f"(d[2]), "+f"(d[3])
                 : "r"(a0), "r"(a1), "r"(a2), "r"(a3), "r"(b0), "r"(b1));
}

// ---------------- one-time staging ----------------
// W[k,n] row-major (global) -> resident split-bf16 fragment arrays (full K)
__device__ __forceinline__ void stage_W(uint32_t* sm, int woff,
                                        const float* __restrict__ W, int tid) {
#pragma unroll
    for (int i = 0; i < 16; ++i) {
        int p = tid + i * NTHR;                 // 0..8191
        int n = p & 127, P = p >> 7;            // P = global k-pair 0..63
        float a = W[(size_t)(2 * P) * FD + n];
        float b = W[(size_t)(2 * P + 1) * FD + n];
        uint32_t hi, lo; split2(a, b, hi, lo);
        int kc = P >> 4, pp = P & 15, s = pp >> 3, q = pp & 7;
        int half = q >> 2;
        int idx = (kc * 8 + s * 4 + (q & 3)) * 136 + n;
        sm[woff + half * 2 * WARR + idx] = hi;
        sm[woff + half * 2 * WARR + WARR + idx] = lo;
    }
}
// A[row0.., 0:128] row-major -> resident split-bf16 A (full K), zero-pad rows >= nv
__device__ __forceinline__ void stage_A(uint32_t* sm, const float* __restrict__ A,
                                        int row0, int nv, int tid) {
#pragma unroll
    for (int i = 0; i < 16; ++i) {
        int p = tid + i * NTHR;                 // 0..8191
        int row = p >> 6, kp = p & 63;
        float2 v = make_float2(0.f, 0.f);
        if (row < nv) v = *(const float2*)(A + (size_t)(row0 + row) * FD + kp * 2);
        uint32_t hi, lo; split2(v.x, v.y, hi, lo);
        int kc = kp >> 4, pp = kp & 15, s = pp >> 3, q = pp & 7;
        int col = kc * 16 + s * 8 + (q & 3) * 2 + (q >> 2);
        sm[AH_OFF + row * 68 + col] = hi;
        sm[AL_OFF + row * 68 + col] = lo;
    }
}

// ---------------- resident-everything GEMM: no syncs, no stores ----------------
__device__ __forceinline__ void gemm_res(const uint32_t* sm, int woff,
                                         float (&acc)[2][4][4],
                                         int mrow, int ncol0, int qr, int qc) {
#pragma unroll
    for (int kc = 0; kc < 4; ++kc) {
#pragma unroll
        for (int s = 0; s < 2; ++s) {
            uint2 Ah[2][2], Al[2][2];
            int c = kc * 16 + s * 8 + qc * 2;
#pragma unroll
            for (int mi = 0; mi < 2; ++mi) {
                int r0 = mrow + mi * 16 + qr;
                Ah[mi][0] = *(const uint2*)(sm + AH_OFF + r0 * 68 + c);
                Ah[mi][1] = *(const uint2*)(sm + AH_OFF + (r0 + 8) * 68 + c);
                Al[mi][0] = *(const uint2*)(sm + AL_OFF + r0 * 68 + c);
                Al[mi][1] = *(const uint2*)(sm + AL_OFF + (r0 + 8) * 68 + c);
            }
            int brow = (kc * 8 + s * 4 + qc) * 136 + ncol0 + qr;
#pragma unroll
            for (int nb = 0; nb < 4; ++nb) {
                uint32_t b0h = sm[woff + brow + nb * 8];
                uint32_t b0l = sm[woff + WARR + brow + nb * 8];
                uint32_t b1h = sm[woff + 2 * WARR + brow + nb * 8];
                uint32_t b1l = sm[woff + 3 * WARR + brow + nb * 8];
#pragma unroll
                for (int mi = 0; mi < 2; ++mi) {
                    mma16(acc[mi][nb], Ah[mi][0].x, Ah[mi][1].x, Ah[mi][0].y, Ah[mi][1].y, b0l, b1l);
                    mma16(acc[mi][nb], Al[mi][0].x, Al[mi][1].x, Al[mi][0].y, Al[mi][1].y, b0h, b1h);
                    mma16(acc[mi][nb], Ah[mi][0].x, Ah[mi][1].x, Ah[mi][0].y, Ah[mi][1].y, b0h, b1h);
                }
            }
        }
    }
}

// stage h fragments (post-ssp) back into resident A (proven R11 mapping)
__device__ __forceinline__ void stage_h(uint32_t* sm, const float (&h)[2][4][4],
                                        int wid_n, int mrow, int qr, int qc) {
#pragma unroll
    for (int mi = 0; mi < 2; ++mi)
#pragma unroll
        for (int nb = 0; nb < 4; ++nb) {
            int col = wid_n * 16 + (nb >> 1) * 8 + qc * 2 + (nb & 1);
            int rlo = mrow + mi * 16 + qr;
            uint32_t hi, lo;
            split2(h[mi][nb][0], h[mi][nb][1], hi, lo);
            sm[AH_OFF + rlo * 68 + col] = hi;
            sm[AL_OFF + rlo * 68 + col] = lo;
            split2(h[mi][nb][2], h[mi][nb][3], hi, lo);
            sm[AH_OFF + (rlo + 8) * 68 + col] = hi;
            sm[AL_OFF + (rlo + 8) * 68 + col] = lo;
        }
}

__device__ __forceinline__ void bias_ssp(float (&a)[2][4][4], const float* __restrict__ b,
                                         int ncol0, int qc) {
#pragma unroll
    for (int nb = 0; nb < 4; ++nb) {
        float2 bb = *(const float2*)(b + ncol0 + nb * 8 + 2 * qc);
#pragma unroll
        for (int mi = 0; mi < 2; ++mi) {
            a[mi][nb][0] = ssp_f(a[mi][nb][0] + bb.x);
            a[mi][nb][1] = ssp_f(a[mi][nb][1] + bb.y);
            a[mi][nb][2] = ssp_f(a[mi][nb][2] + bb.x);
            a[mi][nb][3] = ssp_f(a[mi][nb][3] + bb.y);
        }
    }
}

// ---------------- kernels ----------------
__global__ void k_zero(int n4) {
    int i = blockIdx.x * blockDim.x + threadIdx.x;
    if (i < n4) ((float4*)g_conv)[i] = make_float4(0.f, 0.f, 0.f, 0.f);
}

__global__ void __launch_bounds__(NTHR, 1) k_in2fac(const float* __restrict__ x,
                                                    const float* __restrict__ Wi,
                                                    int N, int nTiles) {
    extern __shared__ uint32_t sm[];
    int tid = threadIdx.x, lane = tid & 31, wid = tid >> 5;
    int qr = lane >> 2, qc = lane & 3;
    int mrow = (wid >> 2) * 32, ncol0 = (wid & 3) * 32;

    stage_W(sm, WOFF1, Wi, tid);
    __syncthreads();

    for (int t = blockIdx.x; t < nTiles; t += gridDim.x) {
        int row0 = t * 128;
        stage_A(sm, x, row0, min(128, N - row0), tid);
        __syncthreads();

        float acc[2][4][4] = {};
        gemm_res(sm, WOFF1, acc, mrow, ncol0, qr, qc);

#pragma unroll
        for (int mi = 0; mi < 2; ++mi)
#pragma unroll
            for (int rh = 0; rh < 2; ++rh) {
                int row = row0 + mrow + mi * 16 + qr + rh * 8;
                if (row < N) {
#pragma unroll
                    for (int nb = 0; nb < 4; ++nb)
                        *(float2*)(g_fbuf + (size_t)row * FD + ncol0 + nb * 8 + 2 * qc) =
                            make_float2(acc[mi][nb][rh * 2], acc[mi][nb][rh * 2 + 1]);
                }
            }
        __syncthreads();   // A region reused next tile
    }
}

__global__ void __launch_bounds__(NTHR, 1) k_edge(const float* __restrict__ dijk,
                                                  const float* __restrict__ W1,
                                                  const float* __restrict__ b1,
                                                  const float* __restrict__ W2,
                                                  const float* __restrict__ b2,
                                                  const int* __restrict__ idx_j,
                                                  const int* __restrict__ seg_i,
                                                  int E, int nTiles) {
    extern __shared__ uint32_t sm[];
    int tid = threadIdx.x, lane = tid & 31, wid = tid >> 5;
    int qr = lane >> 2, qc = lane & 3;
    int mrow = (wid >> 2) * 32, ncol0 = (wid & 3) * 32;

    stage_W(sm, WOFF1, W1, tid);
    stage_W(sm, WOFF2, W2, tid);
    if (tid < FD) {
        ((float*)(sm + B1_OFF))[tid] = b1[tid];
        ((float*)(sm + B2_OFF))[tid] = b2[tid];
    }
    __syncthreads();

    const float* bb1 = (const float*)(sm + B1_OFF);
    const float* bb2 = (const float*)(sm + B2_OFF);
    float* sW = (float*)(sm + SW_OFF);
    int tx = tid & 31, ty = tid >> 5;    // RLE epilogue mapping
    int col0 = tx * 4;

    for (int t = blockIdx.x; t < nTiles; t += gridDim.x) {
        int e0 = t * 128;
        stage_A(sm, dijk, e0, min(128, E - e0), tid);
        __syncthreads();

        // h = ssp(dijk @ W1 + b1)
        float acc[2][4][4] = {};
        gemm_res(sm, WOFF1, acc, mrow, ncol0, qr, qc);
        bias_ssp(acc, bb1, ncol0, qc);
        __syncthreads();                 // all warps done reading A
        stage_h(sm, acc, wid & 3, mrow, qr, qc);
        __syncthreads();

        // w = ssp(h @ W2 + b2)   (seg_j == arange -> first segment_sum identity)
#pragma unroll
        for (int mi = 0; mi < 2; ++mi)
#pragma unroll
            for (int nb = 0; nb < 4; ++nb)
#pragma unroll
                for (int r = 0; r < 4; ++r) acc[mi][nb][r] = 0.f;
        gemm_res(sm, WOFF2, acc, mrow, ncol0, qr, qc);
        bias_ssp(acc, bb2, ncol0, qc);
        __syncthreads();                 // all warps done reading h before sW overwrite

        // stage w to fp32 smem (overlaps A region)
#pragma unroll
        for (int mi = 0; mi < 2; ++mi)
#pragma unroll
            for (int rh = 0; rh < 2; ++rh) {
                int row = mrow + mi * 16 + qr + rh * 8;
#pragma unroll
                for (int nb = 0; nb < 4; ++nb)
                    *(float2*)(sW + row * 132 + ncol0 + nb * 8 + 2 * qc) =
                        make_float2(acc[mi][nb][rh * 2], acc[mi][nb][rh * 2 + 1]);
            }
        __syncthreads();

        // wf = w * f[idx_j]; RLE-compressed segmented atomicAdd into g_conv[seg_i]
        {
            float accv[4];
            int cur = -1;
#pragma unroll
            for (int rr = 0; rr < 8; ++rr) {
                int lr = ty * 8 + rr;
                int e = e0 + lr;
                if (e < E) {
                    int j = idx_j[e];
                    float4 f0 = *(const float4*)(g_fbuf + (size_t)j * FD + col0);
                    float4 w0 = *(const float4*)(sW + lr * 132 + col0);
                    float wf[4] = { w0.x * f0.x, w0.y * f0.y, w0.z * f0.z, w0.w * f0.w };
                    int s = seg_i[e];
                    if (s != cur) {
                        if (cur >= 0) {
                            float* dst = g_conv + (size_t)cur * FD + col0;
#pragma unroll
                            for (int c = 0; c < 4; ++c) atomicAdd(dst + c, accv[c]);
                        }
                        cur = s;
#pragma unroll
                        for (int c = 0; c < 4; ++c) accv[c] = wf[c];
                    } else {
#pragma unroll
                        for (int c = 0; c < 4; ++c) accv[c] += wf[c];
                    }
                }
            }
            if (cur >= 0) {
                float* dst = g_conv + (size_t)cur * FD + col0;
#pragma unroll
                for (int c = 0; c < 4; ++c) atomicAdd(dst + c, accv[c]);
            }
        }
        __syncthreads();                 // sW/A region reused next tile
    }
}

__global__ void __launch_bounds__(NTHR, 1) k_atom(const float* __restrict__ x,
                                                  const float* __restrict__ Wf,
                                                  const float* __restrict__ bf,
                                                  const float* __restrict__ Wd,
                                                  const float* __restrict__ bd,
                                                  float* __restrict__ out,
                                                  int N, int nTiles, int hasv) {
    extern __shared__ uint32_t sm[];
    int tid = threadIdx.x, lane = tid & 31, wid = tid >> 5;
    int qr = lane >> 2, qc = lane & 3;
    int mrow = (wid >> 2) * 32, ncol0 = (wid & 3) * 32;

    stage_W(sm, WOFF1, Wf, tid);
    stage_W(sm, WOFF2, Wd, tid);
    if (tid < FD) {
        ((float*)(sm + B1_OFF))[tid] = bf[tid];
        ((float*)(sm + B2_OFF))[tid] = bd[tid];
    }
    __syncthreads();

    const float* bb1 = (const float*)(sm + B1_OFF);
    const float* bb2 = (const float*)(sm + B2_OFF);

    for (int t = blockIdx.x; t < nTiles; t += gridDim.x) {
        int row0 = t * 128;
        stage_A(sm, (const float*)g_conv, row0, min(128, N - row0), tid);
        __syncthreads();

        // c = ssp(conv @ W_fac2out + b_fac2out)
        float acc[2][4][4] = {};
        gemm_res(sm, WOFF1, acc, mrow, ncol0, qr, qc);
        bias_ssp(acc, bb1, ncol0, qc);
        __syncthreads();
        stage_h(sm, acc, wid & 3, mrow, qr, qc);
        __syncthreads();

        // v = c @ W_dense + b_dense;  y = x + v
#pragma unroll
        for (int mi = 0; mi < 2; ++mi)
#pragma unroll
            for (int nb = 0; nb < 4; ++nb)
#pragma unroll
                for (int r = 0; r < 4; ++r) acc[mi][nb][r] = 0.f;
        gemm_res(sm, WOFF2, acc, mrow, ncol0, qr, qc);

#pragma unroll
        for (int mi = 0; mi < 2; ++mi)
#pragma unroll
            for (int rh = 0; rh < 2; ++rh) {
                int row = row0 + mrow + mi * 16 + qr + rh * 8;
                if (row < N) {
#pragma unroll
                    for (int nb = 0; nb < 4; ++nb) {
                        int col = ncol0 + nb * 8 + 2 * qc;
                        float2 bb = *(const float2*)(bb2 + col);
                        float2 xv = *(const float2*)(x + (size_t)row * FD + col);
                        float2 vv = make_float2(acc[mi][nb][rh * 2] + bb.x,
                                                acc[mi][nb][rh * 2 + 1] + bb.y);
                        *(float2*)(out + (size_t)row * FD + col) =
                            make_float2(xv.x + vv.x, xv.y + vv.y);
                        if (hasv)
                            *(float2*)(out + (size_t)N * FD + (size_t)row * FD + col) = vv;
                    }
                }
            }
        __syncthreads();                 // A region reused next tile
    }
}

extern "C" void kernel_launch(void* const* d_in, const int* in_sizes, int n_in,
                              void* d_out, int out_size) {
    const float* x    = (const float*)d_in[0];
    const float* dijk = (const float*)d_in[1];
    const int* idx_j  = (const int*)d_in[2];
    const int* seg_i  = (const int*)d_in[3];
    int wb = 4;
    while (wb < n_in && in_sizes[wb] != FD * FD) ++wb;
    const float* W1 = (const float*)d_in[wb + 0];
    const float* b1 = (const float*)d_in[wb + 1];
    const float* W2 = (const float*)d_in[wb + 2];
    const float* b2 = (const float*)d_in[wb + 3];
    const float* Wi = (const float*)d_in[wb + 4];
    const float* Wf = (const float*)d_in[wb + 5];
    const float* bf = (const float*)d_in[wb + 6];
    const float* Wd = (const float*)d_in[wb + 7];
    const float* bd = (const float*)d_in[wb + 8];

    int N = in_sizes[0] / FD;
    int E = in_sizes[1] / FD;
    float* out = (float*)d_out;
    int hasv = (out_size >= 2 * N * FD) ? 1 : 0;

    cudaFuncSetAttribute(k_in2fac, cudaFuncAttributeMaxDynamicSharedMemorySize, SMEM_BYTES);
    cudaFuncSetAttribute(k_edge,   cudaFuncAttributeMaxDynamicSharedMemorySize, SMEM_BYTES);
    cudaFuncSetAttribute(k_atom,   cudaFuncAttributeMaxDynamicSharedMemorySize, SMEM_BYTES);

    int nTilesN = (N + 127) / 128;
    int nTilesE = (E + 127) / 128;
    int n4 = (N * FD) / 4;
    int gN = nTilesN < 148 ? nTilesN : 148;
    int gE = nTilesE < 148 ? nTilesE : 148;

    k_zero<<<(n4 + 255) / 256, 256>>>(n4);
    k_in2fac<<<gN, NTHR, SMEM_BYTES>>>(x, Wi, N, nTilesN);
    k_edge<<<gE, NTHR, SMEM_BYTES>>>(dijk, W1, b1, W2, b2, idx_j, seg_i, E, nTilesE);
    k_atom<<<gN, NTHR, SMEM_BYTES>>>(x, Wf, bf, Wd, bd, out, N, nTilesN, hasv);
}

// round 17
// speedup vs baseline: 1.0077x; 1.0005x over previous
#include <cuda_runtime.h>
#include <cuda_bf16.h>
#include <cstdint>

#define FD   128
#define NTHR 512
#define MAXN 50048

// ---------------- scratch (no allocations allowed) ----------------
__device__ float g_fbuf[(size_t)MAXN * FD];   // x @ W_in2fac
__device__ float g_conv[(size_t)MAXN * FD];   // segment-sum accumulator

// ---------------- smem layout (uint32 offsets) ----------------
// Per weight matrix: 4 arrays (B0H,B0L,B1H,B1L), each 32 rows x pitch 136 u32.
#define WARR  4352                 /* u32 per array */
#define WOFF1 0                    /* weight 1: 4*WARR = 17408 u32 */
#define WOFF2 17408                /* weight 2 */
#define AH_OFF 34816               /* A hi: 128 rows x pitch 68 */
#define AL_OFF 43520               /* A lo */
#define SW_OFF 34816               /* fp32 w stage (128x132) overlaps A region */
#define B1_OFF 52224               /* bias1 (128 f32) */
#define B2_OFF 52352               /* bias2 */
#define SMEM_U32 52480
#define SMEM_BYTES (SMEM_U32 * 4)  /* 209920 B -> 1 CTA/SM */

__device__ __forceinline__ float ssp_f(float x) {
    float t = __expf(-fabsf(x));
    return fmaxf(x, 0.0f) + __logf(1.0f + t) - 0.6931471805599453f;
}
// two consecutive-k floats -> bf16x2 hi word + bf16x2 residual-lo word
__device__ __forceinline__ void split2(float x0, float x1, uint32_t& hi, uint32_t& lo) {
    __nv_bfloat162 h = __floats2bfloat162_rn(x0, x1);
    float r0 = x0 - __bfloat162float(h.x);
    float r1 = x1 - __bfloat162float(h.y);
    __nv_bfloat162 l = __floats2bfloat162_rn(r0, r1);
    hi = *reinterpret_cast<uint32_t*>(&h);
    lo = *reinterpret_cast<uint32_t*>(&l);
}
__device__ __forceinline__ void mma16(float* d, uint32_t a0, uint32_t a1, uint32_t a2, uint32_t a3,
                                      uint32_t b0, uint32_t b1) {
    asm volatile("mma.sync.aligned.m16n8k16.row.col.f32.bf16.bf16.f32 "
                 "{%0,%1,%2,%3}, {%4,%5,%6,%7}, {%8,%9}, {%0,%1,%2,%3};"
                 : "+f"(d[0]), "+f"(d[1]), "+f"(d[2]), "+f"(d[3])
                 : "r"(a0), "r"(a1), "r"(a2), "r"(a3), "r"(b0), "r"(b1));
}

// ---------------- one-time staging ----------------
// W[k,n] row-major (global) -> resident split-bf16 fragment arrays (full K)
__device__ __forceinline__ void stage_W(uint32_t* sm, int woff,
                                        const float* __restrict__ W, int tid) {
#pragma unroll
    for (int i = 0; i < 16; ++i) {
        int p = tid + i * NTHR;                 // 0..8191
        int n = p & 127, P = p >> 7;            // P = global k-pair 0..63
        float a = W[(size_t)(2 * P) * FD + n];
        float b = W[(size_t)(2 * P + 1) * FD + n];
        uint32_t hi, lo; split2(a, b, hi, lo);
        int kc = P >> 4, pp = P & 15, s = pp >> 3, q = pp & 7;
        int half = q >> 2;
        int idx = (kc * 8 + s * 4 + (q & 3)) * 136 + n;
        sm[woff + half * 2 * WARR + idx] = hi;
        sm[woff + half * 2 * WARR + WARR + idx] = lo;
    }
}
// A[row0.., 0:128] row-major -> resident split-bf16 A (full K), zero-pad rows >= nv
__device__ __forceinline__ void stage_A(uint32_t* sm, const float* __restrict__ A,
                                        int row0, int nv, int tid) {
#pragma unroll
    for (int i = 0; i < 16; ++i) {
        int p = tid + i * NTHR;                 // 0..8191
        int row = p >> 6, kp = p & 63;
        float2 v = make_float2(0.f, 0.f);
        if (row < nv) v = *(const float2*)(A + (size_t)(row0 + row) * FD + kp * 2);
        uint32_t hi, lo; split2(v.x, v.y, hi, lo);
        int kc = kp >> 4, pp = kp & 15, s = pp >> 3, q = pp & 7;
        int col = kc * 16 + s * 8 + (q & 3) * 2 + (q >> 2);
        sm[AH_OFF + row * 68 + col] = hi;
        sm[AL_OFF + row * 68 + col] = lo;
    }
}

// ---------------- resident-everything GEMM: no syncs, no stores ----------------
__device__ __forceinline__ void gemm_res(const uint32_t* sm, int woff,
                                         float (&acc)[2][4][4],
                                         int mrow, int ncol0, int qr, int qc) {
#pragma unroll
    for (int kc = 0; kc < 4; ++kc) {
#pragma unroll
        for (int s = 0; s < 2; ++s) {
            uint2 Ah[2][2], Al[2][2];
            int c = kc * 16 + s * 8 + qc * 2;
#pragma unroll
            for (int mi = 0; mi < 2; ++mi) {
                int r0 = mrow + mi * 16 + qr;
                Ah[mi][0] = *(const uint2*)(sm + AH_OFF + r0 * 68 + c);
                Ah[mi][1] = *(const uint2*)(sm + AH_OFF + (r0 + 8) * 68 + c);
                Al[mi][0] = *(const uint2*)(sm + AL_OFF + r0 * 68 + c);
                Al[mi][1] = *(const uint2*)(sm + AL_OFF + (r0 + 8) * 68 + c);
            }
            int brow = (kc * 8 + s * 4 + qc) * 136 + ncol0 + qr;
#pragma unroll
            for (int nb = 0; nb < 4; ++nb) {
                uint32_t b0h = sm[woff + brow + nb * 8];
                uint32_t b0l = sm[woff + WARR + brow + nb * 8];
                uint32_t b1h = sm[woff + 2 * WARR + brow + nb * 8];
                uint32_t b1l = sm[woff + 3 * WARR + brow + nb * 8];
#pragma unroll
                for (int mi = 0; mi < 2; ++mi) {
                    mma16(acc[mi][nb], Ah[mi][0].x, Ah[mi][1].x, Ah[mi][0].y, Ah[mi][1].y, b0l, b1l);
                    mma16(acc[mi][nb], Al[mi][0].x, Al[mi][1].x, Al[mi][0].y, Al[mi][1].y, b0h, b1h);
                    mma16(acc[mi][nb], Ah[mi][0].x, Ah[mi][1].x, Ah[mi][0].y, Ah[mi][1].y, b0h, b1h);
                }
            }
        }
    }
}

// stage h fragments (post-ssp) back into resident A (proven R11 mapping)
__device__ __forceinline__ void stage_h(uint32_t* sm, const float (&h)[2][4][4],
                                        int wid_n, int mrow, int qr, int qc) {
#pragma unroll
    for (int mi = 0; mi < 2; ++mi)
#pragma unroll
        for (int nb = 0; nb < 4; ++nb) {
            int col = wid_n * 16 + (nb >> 1) * 8 + qc * 2 + (nb & 1);
            int rlo = mrow + mi * 16 + qr;
            uint32_t hi, lo;
            split2(h[mi][nb][0], h[mi][nb][1], hi, lo);
            sm[AH_OFF + rlo * 68 + col] = hi;
            sm[AL_OFF + rlo * 68 + col] = lo;
            split2(h[mi][nb][2], h[mi][nb][3], hi, lo);
            sm[AH_OFF + (rlo + 8) * 68 + col] = hi;
            sm[AL_OFF + (rlo + 8) * 68 + col] = lo;
        }
}

__device__ __forceinline__ void bias_ssp(float (&a)[2][4][4], const float* __restrict__ b,
                                         int ncol0, int qc) {
#pragma unroll
    for (int nb = 0; nb < 4; ++nb) {
        float2 bb = *(const float2*)(b + ncol0 + nb * 8 + 2 * qc);
#pragma unroll
        for (int mi = 0; mi < 2; ++mi) {
            a[mi][nb][0] = ssp_f(a[mi][nb][0] + bb.x);
            a[mi][nb][1] = ssp_f(a[mi][nb][1] + bb.y);
            a[mi][nb][2] = ssp_f(a[mi][nb][2] + bb.x);
            a[mi][nb][3] = ssp_f(a[mi][nb][3] + bb.y);
        }
    }
}

// ---------------- kernels ----------------
__global__ void k_zero(int n4) {
    int i = blockIdx.x * blockDim.x + threadIdx.x;
    if (i < n4) ((float4*)g_conv)[i] = make_float4(0.f, 0.f, 0.f, 0.f);
}

__global__ void __launch_bounds__(NTHR, 1) k_in2fac(const float* __restrict__ x,
                                                    const float* __restrict__ Wi,
                                                    int N, int nTiles) {
    extern __shared__ uint32_t sm[];
    int tid = threadIdx.x, lane = tid & 31, wid = tid >> 5;
    int qr = lane >> 2, qc = lane & 3;
    int mrow = (wid >> 2) * 32, ncol0 = (wid & 3) * 32;

    stage_W(sm, WOFF1, Wi, tid);
    __syncthreads();

    for (int t = blockIdx.x; t < nTiles; t += gridDim.x) {
        int row0 = t * 128;
        stage_A(sm, x, row0, min(128, N - row0), tid);
        __syncthreads();

        float acc[2][4][4] = {};
        gemm_res(sm, WOFF1, acc, mrow, ncol0, qr, qc);

#pragma unroll
        for (int mi = 0; mi < 2; ++mi)
#pragma unroll
            for (int rh = 0; rh < 2; ++rh) {
                int row = row0 + mrow + mi * 16 + qr + rh * 8;
                if (row < N) {
#pragma unroll
                    for (int nb = 0; nb < 4; ++nb)
                        *(float2*)(g_fbuf + (size_t)row * FD + ncol0 + nb * 8 + 2 * qc) =
                            make_float2(acc[mi][nb][rh * 2], acc[mi][nb][rh * 2 + 1]);
                }
            }
        __syncthreads();   // A region reused next tile
    }
}

__global__ void __launch_bounds__(NTHR, 1) k_edge(const float* __restrict__ dijk,
                                                  const float* __restrict__ W1,
                                                  const float* __restrict__ b1,
                                                  const float* __restrict__ W2,
                                                  const float* __restrict__ b2,
                                                  const int* __restrict__ idx_j,
                                                  const int* __restrict__ seg_i,
                                                  int E, int nTiles) {
    extern __shared__ uint32_t sm[];
    int tid = threadIdx.x, lane = tid & 31, wid = tid >> 5;
    int qr = lane >> 2, qc = lane & 3;
    int mrow = (wid >> 2) * 32, ncol0 = (wid & 3) * 32;

    stage_W(sm, WOFF1, W1, tid);
    stage_W(sm, WOFF2, W2, tid);
    if (tid < FD) {
        ((float*)(sm + B1_OFF))[tid] = b1[tid];
        ((float*)(sm + B2_OFF))[tid] = b2[tid];
    }
    __syncthreads();

    const float* bb1 = (const float*)(sm + B1_OFF);
    const float* bb2 = (const float*)(sm + B2_OFF);
    float* sW = (float*)(sm + SW_OFF);
    int tx = tid & 31, ty = tid >> 5;    // RLE epilogue mapping
    int col0 = tx * 4;

    for (int t = blockIdx.x; t < nTiles; t += gridDim.x) {
        int e0 = t * 128;
        stage_A(sm, dijk, e0, min(128, E - e0), tid);
        __syncthreads();

        // h = ssp(dijk @ W1 + b1)
        float acc[2][4][4] = {};
        gemm_res(sm, WOFF1, acc, mrow, ncol0, qr, qc);
        bias_ssp(acc, bb1, ncol0, qc);
        __syncthreads();                 // all warps done reading A
        stage_h(sm, acc, wid & 3, mrow, qr, qc);
        __syncthreads();

        // w = ssp(h @ W2 + b2)   (seg_j == arange -> first segment_sum identity)
#pragma unroll
        for (int mi = 0; mi < 2; ++mi)
#pragma unroll
            for (int nb = 0; nb < 4; ++nb)
#pragma unroll
                for (int r = 0; r < 4; ++r) acc[mi][nb][r] = 0.f;
        gemm_res(sm, WOFF2, acc, mrow, ncol0, qr, qc);
        bias_ssp(acc, bb2, ncol0, qc);
        __syncthreads();                 // all warps done reading h before sW overwrite

        // stage w to fp32 smem (overlaps A region)
#pragma unroll
        for (int mi = 0; mi < 2; ++mi)
#pragma unroll
            for (int rh = 0; rh < 2; ++rh) {
                int row = mrow + mi * 16 + qr + rh * 8;
#pragma unroll
                for (int nb = 0; nb < 4; ++nb)
                    *(float2*)(sW + row * 132 + ncol0 + nb * 8 + 2 * qc) =
                        make_float2(acc[mi][nb][rh * 2], acc[mi][nb][rh * 2 + 1]);
            }
        __syncthreads();

        // wf = w * f[idx_j]; RLE-compressed segmented atomicAdd into g_conv[seg_i]
        {
            float accv[4];
            int cur = -1;
#pragma unroll
            for (int rr = 0; rr < 8; ++rr) {
                int lr = ty * 8 + rr;
                int e = e0 + lr;
                if (e < E) {
                    int j = idx_j[e];
                    float4 f0 = *(const float4*)(g_fbuf + (size_t)j * FD + col0);
                    float4 w0 = *(const float4*)(sW + lr * 132 + col0);
                    float wf[4] = { w0.x * f0.x, w0.y * f0.y, w0.z * f0.z, w0.w * f0.w };
                    int s = seg_i[e];
                    if (s != cur) {
                        if (cur >= 0) {
                            float* dst = g_conv + (size_t)cur * FD + col0;
#pragma unroll
                            for (int c = 0; c < 4; ++c) atomicAdd(dst + c, accv[c]);
                        }
                        cur = s;
#pragma unroll
                        for (int c = 0; c < 4; ++c) accv[c] = wf[c];
                    } else {
#pragma unroll
                        for (int c = 0; c < 4; ++c) accv[c] += wf[c];
                    }
                }
            }
            if (cur >= 0) {
                float* dst = g_conv + (size_t)cur * FD + col0;
#pragma unroll
                for (int c = 0; c < 4; ++c) atomicAdd(dst + c, accv[c]);
            }
        }
        __syncthreads();                 // sW/A region reused next tile
    }
}

__global__ void __launch_bounds__(NTHR, 1) k_atom(const float* __restrict__ x,
                                                  const float* __restrict__ Wf,
                                                  const float* __restrict__ bf,
                                                  const float* __restrict__ Wd,
                                                  const float* __restrict__ bd,
                                                  float* __restrict__ out,
                                                  int N, int nTiles, int hasv) {
    extern __shared__ uint32_t sm[];
    int tid = threadIdx.x, lane = tid & 31, wid = tid >> 5;
    int qr = lane >> 2, qc = lane & 3;
    int mrow = (wid >> 2) * 32, ncol0 = (wid & 3) * 32;

    stage_W(sm, WOFF1, Wf, tid);
    stage_W(sm, WOFF2, Wd, tid);
    if (tid < FD) {
        ((float*)(sm + B1_OFF))[tid] = bf[tid];
        ((float*)(sm + B2_OFF))[tid] = bd[tid];
    }
    __syncthreads();

    const float* bb1 = (const float*)(sm + B1_OFF);
    const float* bb2 = (const float*)(sm + B2_OFF);

    for (int t = blockIdx.x; t < nTiles; t += gridDim.x) {
        int row0 = t * 128;
        stage_A(sm, (const float*)g_conv, row0, min(128, N - row0), tid);
        __syncthreads();

        // c = ssp(conv @ W_fac2out + b_fac2out)
        float acc[2][4][4] = {};
        gemm_res(sm, WOFF1, acc, mrow, ncol0, qr, qc);
        bias_ssp(acc, bb1, ncol0, qc);
        __syncthreads();
        stage_h(sm, acc, wid & 3, mrow, qr, qc);
        __syncthreads();

        // v = c @ W_dense + b_dense;  y = x + v
#pragma unroll
        for (int mi = 0; mi < 2; ++mi)
#pragma unroll
            for (int nb = 0; nb < 4; ++nb)
#pragma unroll
                for (int r = 0; r < 4; ++r) acc[mi][nb][r] = 0.f;
        gemm_res(sm, WOFF2, acc, mrow, ncol0, qr, qc);

#pragma unroll
        for (int mi = 0; mi < 2; ++mi)
#pragma unroll
            for (int rh = 0; rh < 2; ++rh) {
                int row = row0 + mrow + mi * 16 + qr + rh * 8;
                if (row < N) {
#pragma unroll
                    for (int nb = 0; nb < 4; ++nb) {
                        int col = ncol0 + nb * 8 + 2 * qc;
                        float2 bb = *(const float2*)(bb2 + col);
                        float2 xv = *(const float2*)(x + (size_t)row * FD + col);
                        float2 vv = make_float2(acc[mi][nb][rh * 2] + bb.x,
                                                acc[mi][nb][rh * 2 + 1] + bb.y);
                        *(float2*)(out + (size_t)row * FD + col) =
                            make_float2(xv.x + vv.x, xv.y + vv.y);
                        if (hasv)
                            *(float2*)(out + (size_t)N * FD + (size_t)row * FD + col) = vv;
                    }
                }
            }
        __syncthreads();                 // A region reused next tile
    }
}

extern "C" void kernel_launch(void* const* d_in, const int* in_sizes, int n_in,
                              void* d_out, int out_size) {
    const float* x    = (const float*)d_in[0];
    const float* dijk = (const float*)d_in[1];
    const int* idx_j  = (const int*)d_in[2];
    const int* seg_i  = (const int*)d_in[3];
    int wb = 4;
    while (wb < n_in && in_sizes[wb] != FD * FD) ++wb;
    const float* W1 = (const float*)d_in[wb + 0];
    const float* b1 = (const float*)d_in[wb + 1];
    const float* W2 = (const float*)d_in[wb + 2];
    const float* b2 = (const float*)d_in[wb + 3];
    const float* Wi = (const float*)d_in[wb + 4];
    const float* Wf = (const float*)d_in[wb + 5];
    const float* bf = (const float*)d_in[wb + 6];
    const float* Wd = (const float*)d_in[wb + 7];
    const float* bd = (const float*)d_in[wb + 8];

    int N = in_sizes[0] / FD;
    int E = in_sizes[1] / FD;
    float* out = (float*)d_out;
    int hasv = (out_size >= 2 * N * FD) ? 1 : 0;

    cudaFuncSetAttribute(k_in2fac, cudaFuncAttributeMaxDynamicSharedMemorySize, SMEM_BYTES);
    cudaFuncSetAttribute(k_edge,   cudaFuncAttributeMaxDynamicSharedMemorySize, SMEM_BYTES);
    cudaFuncSetAttribute(k_atom,   cudaFuncAttributeMaxDynamicSharedMemorySize, SMEM_BYTES);

    int nTilesN = (N + 127) / 128;
    int nTilesE = (E + 127) / 128;
    int n4 = (N * FD) / 4;
    int gN = nTilesN < 148 ? nTilesN : 148;
    int gE = nTilesE < 148 ? nTilesE : 148;

    k_zero<<<(n4 + 255) / 256, 256>>>(n4);
    k_in2fac<<<gN, NTHR, SMEM_BYTES>>>(x, Wi, N, nTilesN);
    k_edge<<<gE, NTHR, SMEM_BYTES>>>(dijk, W1, b1, W2, b2, idx_j, seg_i, E, nTilesE);
    k_atom<<<gN, NTHR, SMEM_BYTES>>>(x, Wf, bf, Wd, bd, out, N, nTilesN, hasv);
}